// round 3
// baseline (speedup 1.0000x reference)
#include <cuda_runtime.h>

// Problem constants (RGCNCell: N=50000, E=800000, D=200, R=500, L=2)
#define D        200
#define D4       50
#define MAXN     50000
#define RRELU_SLOPE 0.22916666666666666f

// Scratch (static __device__ globals — allocation-free rule)
__device__ float g_h0[(size_t)MAXN * D];    // 40 MB
__device__ float g_h1[(size_t)MAXN * D];    // 40 MB
__device__ float g_pre[(size_t)MAXN * D];   // 40 MB
__device__ int   g_indeg[MAXN];

// ---------------------------------------------------------------------------
__global__ void k_zero_int(int* __restrict__ p, int n) {
    int i = blockIdx.x * blockDim.x + threadIdx.x;
    if (i < n) p[i] = 0;
}

__global__ void k_zero_f4(float4* __restrict__ p, int n4) {
    int i = blockIdx.x * blockDim.x + threadIdx.x;
    if (i < n4) p[i] = make_float4(0.f, 0.f, 0.f, 0.f);
}

// h0[i,:] = init[node_id[i],:]
__global__ void k_gather(const float4* __restrict__ init4, const int* __restrict__ nid,
                         float4* __restrict__ h04, int total) {
    int i = blockIdx.x * blockDim.x + threadIdx.x;
    if (i >= total) return;
    int row = i / D4;
    int c   = i % D4;
    h04[i] = init4[(size_t)nid[row] * D4 + c];
}

__global__ void k_indeg(const int* __restrict__ dst, int* __restrict__ indeg, int E) {
    int i = blockIdx.x * blockDim.x + threadIdx.x;
    if (i < E) atomicAdd(&indeg[dst[i]], 1);
}

// pre[dst] += h[src] + rel[etype]   (one warp per edge, v4 reduction atomics)
__global__ void k_edge(const float4* __restrict__ h4, const float4* __restrict__ rel4,
                       const int* __restrict__ src, const int* __restrict__ dst,
                       const int* __restrict__ et, float* __restrict__ pre, int E) {
    int gw   = (blockIdx.x * blockDim.x + threadIdx.x) >> 5;
    int lane = threadIdx.x & 31;
    if (gw >= E) return;
    int s = src[gw], d = dst[gw], t = et[gw];
    const float4* hs = h4   + (size_t)s * D4;
    const float4* rp = rel4 + (size_t)t * D4;
    float* pd = pre + (size_t)d * D;
    for (int c = lane; c < D4; c += 32) {
        float4 hv = hs[c];
        float4 rv = rp[c];
        float x = hv.x + rv.x, y = hv.y + rv.y, z = hv.z + rv.z, w = hv.w + rv.w;
        asm volatile("red.global.add.v4.f32 [%0], {%1,%2,%3,%4};"
                     :: "l"(pd + 4 * c), "f"(x), "f"(y), "f"(z), "f"(w)
                     : "memory");
    }
}

// out = rrelu( (pre*norm) @ Wn + h @ Wl )
// Tiled SGEMM: BM=128, BN=64, BK=8, 256 threads, 8x4 micro-tile per thread.
// K loop runs two phases: phase0 A=pre (scaled by norm), W=Wn; phase1 A=h, W=Wl.
#define BM 128
#define BN 64
#define BK 8
__global__ __launch_bounds__(256) void k_gemm(
    const float* __restrict__ pre, const float* __restrict__ hin,
    const float* __restrict__ norm,
    const float* __restrict__ Wn, const float* __restrict__ Wl,
    float* __restrict__ out, int M) {

    __shared__ float As[BK][BM];
    __shared__ float Bs[BK][BN];

    int tid  = threadIdx.x;
    int tx   = tid & 15;       // micro-tile col group (0..15)
    int ty   = tid >> 4;       // micro-tile row group (0..15)
    int row0 = blockIdx.x * BM;
    int col0 = blockIdx.y * BN;

    float acc[8][4];
#pragma unroll
    for (int i = 0; i < 8; i++)
#pragma unroll
        for (int j = 0; j < 4; j++) acc[i][j] = 0.f;

    int lr  = tid >> 1;        // A-tile load row (0..127)
    int lk  = (tid & 1) * 4;   // A-tile load k offset (0 or 4)
    int bkk = tid >> 4;        // B-tile load k (tid<128 -> 0..7)
    int bc  = (tid & 15) * 4;  // B-tile load col offset (0..60)

    for (int phase = 0; phase < 2; ++phase) {
        const float* A = phase ? hin : pre;
        const float* W = phase ? Wl  : Wn;
        for (int k0 = 0; k0 < D; k0 += BK) {
            // stage gmem loads into registers
            float4 av = make_float4(0.f, 0.f, 0.f, 0.f);
            int grow = row0 + lr;
            if (grow < M) {
                av = *(const float4*)(A + (size_t)grow * D + k0 + lk);
                if (phase == 0) {
                    float nv = __ldg(&norm[grow]);
                    av.x *= nv; av.y *= nv; av.z *= nv; av.w *= nv;
                }
            }
            float4 bv = make_float4(0.f, 0.f, 0.f, 0.f);
            if (tid < 128) {
                int gcol = col0 + bc;
                const float* wp = W + (size_t)(k0 + bkk) * D;
                if (gcol + 3 < D) {
                    bv = *(const float4*)(wp + gcol);
                } else {
                    if (gcol + 0 < D) bv.x = wp[gcol + 0];
                    if (gcol + 1 < D) bv.y = wp[gcol + 1];
                    if (gcol + 2 < D) bv.z = wp[gcol + 2];
                }
            }
            __syncthreads();   // previous iter's compute done
            As[lk + 0][lr] = av.x;
            As[lk + 1][lr] = av.y;
            As[lk + 2][lr] = av.z;
            As[lk + 3][lr] = av.w;
            if (tid < 128) *(float4*)&Bs[bkk][bc] = bv;
            __syncthreads();
#pragma unroll
            for (int kk = 0; kk < BK; ++kk) {
                float a[8], b[4];
#pragma unroll
                for (int i = 0; i < 8; i++) a[i] = As[kk][ty * 8 + i];
#pragma unroll
                for (int j = 0; j < 4; j++) b[j] = Bs[kk][tx * 4 + j];
#pragma unroll
                for (int i = 0; i < 8; i++)
#pragma unroll
                    for (int j = 0; j < 4; j++)
                        acc[i][j] = fmaf(a[i], b[j], acc[i][j]);
            }
        }
    }

#pragma unroll
    for (int i = 0; i < 8; i++) {
        int grow = row0 + ty * 8 + i;
        if (grow >= M) continue;
#pragma unroll
        for (int j = 0; j < 4; j++) {
            int gcol = col0 + tx * 4 + j;
            if (gcol < D) {
                float v = acc[i][j];
                out[(size_t)grow * D + gcol] = (v >= 0.f) ? v : v * RRELU_SLOPE;
            }
        }
    }
}

// Rows with indeg==0 use evolve_loop_weight; pre-row is zero there, so
// out[n] = rrelu(h[n] @ We). Expected ~0 such rows for this graph.
__global__ void k_fixup(const float* __restrict__ hin, const float* __restrict__ We,
                        const int* __restrict__ indeg, float* __restrict__ out, int M) {
    int n = blockIdx.x;
    if (n >= M) return;
    if (indeg[n] != 0) return;
    __shared__ float hrow[D];
    for (int k = threadIdx.x; k < D; k += blockDim.x) hrow[k] = hin[(size_t)n * D + k];
    __syncthreads();
    for (int j = threadIdx.x; j < D; j += blockDim.x) {
        float s = 0.f;
        for (int k = 0; k < D; ++k) s = fmaf(hrow[k], We[(size_t)k * D + j], s);
        out[(size_t)n * D + j] = (s >= 0.f) ? s : s * RRELU_SLOPE;
    }
}

// ---------------------------------------------------------------------------
extern "C" void kernel_launch(void* const* d_in, const int* in_sizes, int n_in,
                              void* d_out, int out_size) {
    const float* init  = (const float*)d_in[0];   // [N, D]
    const float* rel   = (const float*)d_in[1];   // [R, D]
    const float* Wn    = (const float*)d_in[2];   // [L, D, D]
    const float* Wl    = (const float*)d_in[3];   // [L, D, D]
    const float* We    = (const float*)d_in[4];   // [L, D, D]
    const float* norm  = (const float*)d_in[5];   // [N, 1]
    const int*   src   = (const int*)d_in[6];     // [E]
    const int*   dst   = (const int*)d_in[7];     // [E]
    const int*   et    = (const int*)d_in[8];     // [E]
    const int*   nid   = (const int*)d_in[9];     // [N]

    int E = in_sizes[6];
    int N = in_sizes[9];
    int L = in_sizes[2] / (D * D);
    float* out = (float*)d_out;

    void *ph0, *ph1, *ppre, *pindeg;
    cudaGetSymbolAddress(&ph0, g_h0);
    cudaGetSymbolAddress(&ph1, g_h1);
    cudaGetSymbolAddress(&ppre, g_pre);
    cudaGetSymbolAddress(&pindeg, g_indeg);
    float* h0   = (float*)ph0;
    float* h1   = (float*)ph1;
    float* pre  = (float*)ppre;
    int*   indeg = (int*)pindeg;

    int nd4 = N * D4;

    k_zero_int<<<(N + 255) / 256, 256>>>(indeg, N);
    k_gather<<<(nd4 + 255) / 256, 256>>>((const float4*)init, nid, (float4*)h0, nd4);
    k_indeg<<<(E + 255) / 256, 256>>>(dst, indeg, E);

    const float* hin = h0;
    for (int l = 0; l < L; ++l) {
        float* hout = (l == L - 1) ? out : ((hin == h0) ? h1 : h0);

        k_zero_f4<<<(nd4 + 255) / 256, 256>>>((float4*)pre, nd4);

        int eb = (int)(((long long)E * 32 + 255) / 256);
        k_edge<<<eb, 256>>>((const float4*)hin, (const float4*)rel, src, dst, et, pre, E);

        dim3 gg((N + BM - 1) / BM, (D + BN - 1) / BN);
        k_gemm<<<gg, 256>>>(pre, hin, norm, Wn + (size_t)l * D * D,
                            Wl + (size_t)l * D * D, hout, N);

        k_fixup<<<N, 256>>>(hin, We + (size_t)l * D * D, indeg, hout, N);

        hin = hout;
    }
}

// round 5
// speedup vs baseline: 1.1625x; 1.1625x over previous
#include <cuda_runtime.h>
#include <cuda_bf16.h>
#include <cstdint>

// Problem constants (RGCNCell: N=50000, E=800000, D=200, R=500, L=2)
#define D        200
#define D4       50
#define MAXN     50000
#define RRELU_SLOPE 0.22916666666666666f

// GEMM config
#define TILE_M   128
#define TILE_N   64
#define NPAD     256                 // padded GEMM-N (200 -> 256)
#define KPAD     512                 // fused padded K: [0,200)=pre, [256,456)=h
#define KCHUNK   64
#define NCHUNKS  8
#define ROWW     36                  // smem row width in words (72 bf16 = 144B, bank-skewed)

// SMEM layout (words)
#define W_AH     0
#define W_AL     (TILE_M * ROWW)          // 4608
#define W_BH     (2 * TILE_M * ROWW)      // 9216
#define W_BL     (2 * TILE_M * ROWW + TILE_N * ROWW)
#define SMEM_WORDS (2 * TILE_M * ROWW + 2 * TILE_N * ROWW)   // 13824 words
#define SMEM_DYN (SMEM_WORDS * 4)                            // 55296 B

// Scratch (static __device__ globals — allocation-free rule)
__device__ float g_h0[(size_t)MAXN * D];
__device__ float g_h1[(size_t)MAXN * D];
__device__ float g_pre[(size_t)MAXN * D];
__device__ int   g_indeg[MAXN];
__device__ __nv_bfloat16 g_Bhi[2 * (size_t)NPAD * KPAD];   // [L][n][k] split weights
__device__ __nv_bfloat16 g_Blo[2 * (size_t)NPAD * KPAD];

// ---------------------------------------------------------------------------
__global__ void k_zero_int(int* __restrict__ p, int n) {
    int i = blockIdx.x * blockDim.x + threadIdx.x;
    if (i < n) p[i] = 0;
}
__global__ void k_zero_f4(float4* __restrict__ p, int n4) {
    int i = blockIdx.x * blockDim.x + threadIdx.x;
    if (i < n4) p[i] = make_float4(0.f, 0.f, 0.f, 0.f);
}
__global__ void k_gather(const float4* __restrict__ init4, const int* __restrict__ nid,
                         float4* __restrict__ h04, int total) {
    int i = blockIdx.x * blockDim.x + threadIdx.x;
    if (i >= total) return;
    int row = i / D4, c = i % D4;
    h04[i] = init4[(size_t)nid[row] * D4 + c];
}
__global__ void k_indeg(const int* __restrict__ dst, int* __restrict__ indeg, int E) {
    int i = blockIdx.x * blockDim.x + threadIdx.x;
    if (i < E) atomicAdd(&indeg[dst[i]], 1);
}

// pre[dst] += h[src] + rel[etype]   (one warp per edge, v4 reduction atomics)
__global__ void k_edge(const float4* __restrict__ h4, const float4* __restrict__ rel4,
                       const int* __restrict__ src, const int* __restrict__ dst,
                       const int* __restrict__ et, float* __restrict__ pre, int E) {
    int gw   = (blockIdx.x * blockDim.x + threadIdx.x) >> 5;
    int lane = threadIdx.x & 31;
    if (gw >= E) return;
    int s = src[gw], d = dst[gw], t = et[gw];
    const float4* hs = h4   + (size_t)s * D4;
    const float4* rp = rel4 + (size_t)t * D4;
    float* pd = pre + (size_t)d * D;
    for (int c = lane; c < D4; c += 32) {
        float4 hv = hs[c];
        float4 rv = rp[c];
        float x = hv.x + rv.x, y = hv.y + rv.y, z = hv.z + rv.z, w = hv.w + rv.w;
        asm volatile("red.global.add.v4.f32 [%0], {%1,%2,%3,%4};"
                     :: "l"(pd + 4 * c), "f"(x), "f"(y), "f"(z), "f"(w) : "memory");
    }
}

// Split weights into bf16 hi/lo, transposed to [n][k], N padded to 256, fused K:
// k in [0,200) -> Wn[l][k][n], k in [256,456) -> Wl[l][k-256][n], else 0.
__global__ void k_prepB(const float* __restrict__ Wn, const float* __restrict__ Wl,
                        __nv_bfloat16* __restrict__ bhi, __nv_bfloat16* __restrict__ blo,
                        int total) {
    int idx = blockIdx.x * blockDim.x + threadIdx.x;
    if (idx >= total) return;
    int k = idx % KPAD;
    int n = (idx / KPAD) % NPAD;
    int l = idx / (KPAD * NPAD);
    float v = 0.f;
    if (n < D) {
        if (k < D)                        v = Wn[(size_t)l * D * D + (size_t)k * D + n];
        else if (k >= 256 && k < 256 + D) v = Wl[(size_t)l * D * D + (size_t)(k - 256) * D + n];
    }
    __nv_bfloat16 h = __float2bfloat16(v);
    bhi[idx] = h;
    blo[idx] = __float2bfloat16(v - __bfloat162float(h));
}

// ---------------------------------------------------------------------------
__device__ __forceinline__ void mma16816(float* c, const uint32_t* a, uint32_t b0, uint32_t b1) {
    asm volatile("mma.sync.aligned.m16n8k16.row.col.f32.bf16.bf16.f32 "
                 "{%0,%1,%2,%3}, {%4,%5,%6,%7}, {%8,%9}, {%0,%1,%2,%3};"
                 : "+f"(c[0]), "+f"(c[1]), "+f"(c[2]), "+f"(c[3])
                 : "r"(a[0]), "r"(a[1]), "r"(a[2]), "r"(a[3]), "r"(b0), "r"(b1));
}

// pack two fp32 into bf16x2 (lo element in low half), and the residual pair
__device__ __forceinline__ void split2(float a, float b, uint32_t& hi, uint32_t& lo) {
    asm("cvt.rn.bf16x2.f32 %0, %1, %2;" : "=r"(hi) : "f"(b), "f"(a));
    float ha = __uint_as_float(hi << 16);
    float hb = __uint_as_float(hi & 0xFFFF0000u);
    float la = a - ha, lb = b - hb;
    asm("cvt.rn.bf16x2.f32 %0, %1, %2;" : "=r"(lo) : "f"(lb), "f"(la));
}

// out = rrelu( (pre*norm) @ Wn + h @ Wl )   via mma.sync bf16 split-3.
__global__ __launch_bounds__(256, 2)
void k_gemm_tc(const float* __restrict__ pre, const float* __restrict__ hin,
               const float* __restrict__ norm,
               const __nv_bfloat16* __restrict__ bhi, const __nv_bfloat16* __restrict__ blo,
               float* __restrict__ out, int M) {
    extern __shared__ __align__(16) uint32_t sw[];
    int tid  = threadIdx.x;
    int wid  = tid >> 5;
    int lane = tid & 31;
    int g    = lane >> 2;     // group 0..7
    int t    = lane & 3;      // thread-in-group
    int row0 = blockIdx.x * TILE_M;
    int col0 = blockIdx.y * TILE_N;

    // A staging coords: row = tid>>1, 32 cols per half
    int arow    = tid >> 1;
    int acol    = (tid & 1) * 32;
    int grow    = row0 + arow;
    bool rv     = grow < M;
    // B staging coords: half 0 -> hi, half 1 -> lo; 64 rows x 64 cols
    int bhalf   = tid >> 7;
    int bt      = tid & 127;
    int brow    = bt >> 1;
    int bcol    = (bt & 1) * 32;
    const __nv_bfloat16* bsrc0 = (bhalf ? blo : bhi) + (size_t)(col0 + brow) * KPAD + bcol;

    // warp tile
    int m0w = (wid >> 1) * 32;
    int n0w = (wid & 1) * 32;

    float C[2][4][4];
#pragma unroll
    for (int mi = 0; mi < 2; mi++)
#pragma unroll
        for (int ni = 0; ni < 4; ni++)
#pragma unroll
            for (int j = 0; j < 4; j++) C[mi][ni][j] = 0.f;

    float pa[8][4];     // prefetched A (32 floats)
    uint4 pb[4];        // prefetched B (32 bf16)

    // ---- prefetch chunk 0 ----
    {
        const float* rp = pre + (size_t)grow * D;
#pragma unroll
        for (int g4 = 0; g4 < 4; ++g4) {
            int k0 = acol + g4 * 8;
#pragma unroll
            for (int j = 0; j < 8; ++j)
                pa[g4 * 2 + (j >> 2)][j & 3] = (rv && k0 + j < D) ? rp[k0 + j] : 0.f;
        }
#pragma unroll
        for (int j = 0; j < 4; ++j) pb[j] = ((const uint4*)bsrc0)[j];
    }

    for (int c = 0; c < NCHUNKS; ++c) {
        if (c > 0) __syncthreads();      // previous chunk's compute done

        // ---- store staged data to smem ----
        {
            float nv = 1.f;
            if (c < 4) nv = rv ? __ldg(norm + grow) : 0.f;
            int wbase = arow * ROWW + acol / 2;
#pragma unroll
            for (int g4 = 0; g4 < 4; ++g4) {
                float v[8];
#pragma unroll
                for (int j = 0; j < 8; ++j) {
                    v[j] = pa[g4 * 2 + (j >> 2)][j & 3];
                    if (c < 4) v[j] *= nv;
                }
                uint32_t hw[4], lw[4];
#pragma unroll
                for (int j = 0; j < 4; ++j) split2(v[2 * j], v[2 * j + 1], hw[j], lw[j]);
                int wb = wbase + g4 * 4;
                *(uint2*)&sw[W_AH + wb]     = make_uint2(hw[0], hw[1]);
                *(uint2*)&sw[W_AH + wb + 2] = make_uint2(hw[2], hw[3]);
                *(uint2*)&sw[W_AL + wb]     = make_uint2(lw[0], lw[1]);
                *(uint2*)&sw[W_AL + wb + 2] = make_uint2(lw[2], lw[3]);
            }
            int bb = (bhalf ? W_BL : W_BH) + brow * ROWW + bcol / 2;
#pragma unroll
            for (int j = 0; j < 4; ++j) {
                *(uint2*)&sw[bb + j * 4]     = make_uint2(pb[j].x, pb[j].y);
                *(uint2*)&sw[bb + j * 4 + 2] = make_uint2(pb[j].z, pb[j].w);
            }
        }
        __syncthreads();

        // ---- prefetch next chunk (overlaps with compute below) ----
        if (c + 1 < NCHUNKS) {
            int cn = c + 1;
            const float* srcp = (cn < 4) ? pre : hin;
            int kofs = (cn & 3) * KCHUNK;
            const float* rp = srcp + (size_t)grow * D;
#pragma unroll
            for (int g4 = 0; g4 < 4; ++g4) {
                int k0 = kofs + acol + g4 * 8;
                if (rv && k0 + 7 < D) {
                    float4 x = *(const float4*)(rp + k0);
                    float4 y = *(const float4*)(rp + k0 + 4);
                    pa[g4 * 2 + 0][0] = x.x; pa[g4 * 2 + 0][1] = x.y;
                    pa[g4 * 2 + 0][2] = x.z; pa[g4 * 2 + 0][3] = x.w;
                    pa[g4 * 2 + 1][0] = y.x; pa[g4 * 2 + 1][1] = y.y;
                    pa[g4 * 2 + 1][2] = y.z; pa[g4 * 2 + 1][3] = y.w;
                } else {
#pragma unroll
                    for (int j = 0; j < 8; ++j)
                        pa[g4 * 2 + (j >> 2)][j & 3] = (rv && k0 + j < D) ? rp[k0 + j] : 0.f;
                }
            }
            const __nv_bfloat16* bs = bsrc0 + cn * KCHUNK;
#pragma unroll
            for (int j = 0; j < 4; ++j) pb[j] = ((const uint4*)bs)[j];
        }

        // ---- compute: 3 passes x 4 k-steps x (2x4) mma ----
#pragma unroll
        for (int p = 0; p < 3; ++p) {
            const uint32_t* Ap = sw + ((p == 1) ? W_AL : W_AH);
            const uint32_t* Bp = sw + ((p == 2) ? W_BL : W_BH);
#pragma unroll
            for (int s = 0; s < 4; ++s) {
                int wo = s * 8 + t;
                uint32_t af[2][4];
#pragma unroll
                for (int mi = 0; mi < 2; ++mi) {
                    int r = m0w + mi * 16 + g;
                    af[mi][0] = Ap[r * ROWW + wo];
                    af[mi][1] = Ap[(r + 8) * ROWW + wo];
                    af[mi][2] = Ap[r * ROWW + wo + 4];
                    af[mi][3] = Ap[(r + 8) * ROWW + wo + 4];
                }
#pragma unroll
                for (int ni = 0; ni < 4; ++ni) {
                    int n = n0w + ni * 8 + g;
                    uint32_t b0 = Bp[n * ROWW + wo];
                    uint32_t b1 = Bp[n * ROWW + wo + 4];
                    mma16816(C[0][ni], af[0], b0, b1);
                    mma16816(C[1][ni], af[1], b0, b1);
                }
            }
        }
    }

    // ---- epilogue: rrelu + store ----
#pragma unroll
    for (int mi = 0; mi < 2; ++mi) {
        int r0 = row0 + m0w + mi * 16 + g;
#pragma unroll
        for (int ni = 0; ni < 4; ++ni) {
            int cc = col0 + n0w + ni * 8 + t * 2;
            if (cc + 1 < D) {
                if (r0 < M) {
                    float v0 = C[mi][ni][0], v1 = C[mi][ni][1];
                    float2 o;
                    o.x = (v0 >= 0.f) ? v0 : v0 * RRELU_SLOPE;
                    o.y = (v1 >= 0.f) ? v1 : v1 * RRELU_SLOPE;
                    *(float2*)(out + (size_t)r0 * D + cc) = o;
                }
                if (r0 + 8 < M) {
                    float v2 = C[mi][ni][2], v3 = C[mi][ni][3];
                    float2 o;
                    o.x = (v2 >= 0.f) ? v2 : v2 * RRELU_SLOPE;
                    o.y = (v3 >= 0.f) ? v3 : v3 * RRELU_SLOPE;
                    *(float2*)(out + (size_t)(r0 + 8) * D + cc) = o;
                }
            }
        }
    }
}

// Rows with indeg==0 use evolve_loop_weight; pre-row is zero there, so
// out[n] = rrelu(h[n] @ We). Expected ~0 such rows for this graph. (fp32)
__global__ void k_fixup(const float* __restrict__ hin, const float* __restrict__ We,
                        const int* __restrict__ indeg, float* __restrict__ out, int M) {
    int n = blockIdx.x;
    if (n >= M) return;
    if (indeg[n] != 0) return;
    __shared__ float hrow[D];
    for (int k = threadIdx.x; k < D; k += blockDim.x) hrow[k] = hin[(size_t)n * D + k];
    __syncthreads();
    for (int j = threadIdx.x; j < D; j += blockDim.x) {
        float s = 0.f;
        for (int k = 0; k < D; ++k) s = fmaf(hrow[k], We[(size_t)k * D + j], s);
        out[(size_t)n * D + j] = (s >= 0.f) ? s : s * RRELU_SLOPE;
    }
}

// ---------------------------------------------------------------------------
extern "C" void kernel_launch(void* const* d_in, const int* in_sizes, int n_in,
                              void* d_out, int out_size) {
    const float* init  = (const float*)d_in[0];
    const float* rel   = (const float*)d_in[1];
    const float* Wn    = (const float*)d_in[2];
    const float* Wl    = (const float*)d_in[3];
    const float* We    = (const float*)d_in[4];
    const float* norm  = (const float*)d_in[5];
    const int*   src   = (const int*)d_in[6];
    const int*   dst   = (const int*)d_in[7];
    const int*   et    = (const int*)d_in[8];
    const int*   nid   = (const int*)d_in[9];

    int E = in_sizes[6];
    int N = in_sizes[9];
    int L = in_sizes[2] / (D * D);
    float* out = (float*)d_out;

    void *ph0, *ph1, *ppre, *pindeg, *pbhi, *pblo;
    cudaGetSymbolAddress(&ph0, g_h0);
    cudaGetSymbolAddress(&ph1, g_h1);
    cudaGetSymbolAddress(&ppre, g_pre);
    cudaGetSymbolAddress(&pindeg, g_indeg);
    cudaGetSymbolAddress(&pbhi, g_Bhi);
    cudaGetSymbolAddress(&pblo, g_Blo);
    float* h0 = (float*)ph0;
    float* h1 = (float*)ph1;
    float* pre = (float*)ppre;
    int* indeg = (int*)pindeg;
    __nv_bfloat16* Bhi = (__nv_bfloat16*)pbhi;
    __nv_bfloat16* Blo = (__nv_bfloat16*)pblo;

    cudaFuncSetAttribute(k_gemm_tc, cudaFuncAttributeMaxDynamicSharedMemorySize, SMEM_DYN);

    int nd4 = N * D4;
    k_zero_int<<<(N + 255) / 256, 256>>>(indeg, N);
    k_gather<<<(nd4 + 255) / 256, 256>>>((const float4*)init, nid, (float4*)h0, nd4);
    k_indeg<<<(E + 255) / 256, 256>>>(dst, indeg, E);

    int ptot = L * NPAD * KPAD;
    k_prepB<<<(ptot + 255) / 256, 256>>>(Wn, Wl, Bhi, Blo, ptot);

    const float* hin = h0;
    for (int l = 0; l < L; ++l) {
        float* hout = (l == L - 1) ? out : ((hin == h0) ? h1 : h0);

        k_zero_f4<<<(nd4 + 255) / 256, 256>>>((float4*)pre, nd4);

        int eb = (int)(((long long)E * 32 + 255) / 256);
        k_edge<<<eb, 256>>>((const float4*)hin, (const float4*)rel, src, dst, et, pre, E);

        dim3 gg((N + TILE_M - 1) / TILE_M, (NPAD / TILE_N));
        k_gemm_tc<<<gg, 256, SMEM_DYN>>>(pre, hin, norm,
                                         Bhi + (size_t)l * NPAD * KPAD,
                                         Blo + (size_t)l * NPAD * KPAD,
                                         hout, N);

        k_fixup<<<N, 256>>>(hin, We + (size_t)l * D * D, indeg, hout, N);

        hin = hout;
    }
}

// round 6
// speedup vs baseline: 1.3096x; 1.1265x over previous
#include <cuda_runtime.h>
#include <cuda_bf16.h>
#include <cstdint>

// Problem constants (RGCNCell: N=50000, E=800000, D=200, R=500, L=2)
#define D        200
#define D4       50
#define MAXN     50000
#define MAXE     800000
#define RRELU_SLOPE 0.22916666666666666f

// GEMM config
#define TILE_M   128
#define TILE_N   64
#define NPAD     256                 // padded GEMM-N (200 -> 256)
#define KPAD     512                 // fused padded K: [0,200)=pre, [256,456)=h
#define KCHUNK   64
#define NCHUNKS  8
#define ROWW     36                  // smem row width in words (72 bf16, bank-skewed)

// SMEM layout (words)
#define W_AH     0
#define W_AL     (TILE_M * ROWW)
#define W_BH     (2 * TILE_M * ROWW)
#define W_BL     (2 * TILE_M * ROWW + TILE_N * ROWW)
#define SMEM_WORDS (2 * TILE_M * ROWW + 2 * TILE_N * ROWW)
#define SMEM_DYN (SMEM_WORDS * 4)    // 55296 B

// Scratch (static __device__ globals — allocation-free rule)
__device__ float g_h0[(size_t)MAXN * D];
__device__ float g_h1[(size_t)MAXN * D];
__device__ float g_pre[(size_t)MAXN * D];
__device__ int   g_indeg[MAXN];
__device__ int   g_off[MAXN + 1];
__device__ int   g_cursor[MAXN];
__device__ int   g_csr_src[MAXE];
__device__ int   g_csr_et[MAXE];
__device__ __nv_bfloat16 g_Bhi[2 * (size_t)NPAD * KPAD];
__device__ __nv_bfloat16 g_Blo[2 * (size_t)NPAD * KPAD];

// ---------------------------------------------------------------------------
__global__ void k_zero_int(int* __restrict__ p, int n) {
    int i = blockIdx.x * blockDim.x + threadIdx.x;
    if (i < n) p[i] = 0;
}
__global__ void k_gather(const float4* __restrict__ init4, const int* __restrict__ nid,
                         float4* __restrict__ h04, int total) {
    int i = blockIdx.x * blockDim.x + threadIdx.x;
    if (i >= total) return;
    int row = i / D4, c = i % D4;
    h04[i] = init4[(size_t)nid[row] * D4 + c];
}
__global__ void k_indeg(const int* __restrict__ dst, int* __restrict__ indeg, int E) {
    int i = blockIdx.x * blockDim.x + threadIdx.x;
    if (i < E) atomicAdd(&indeg[dst[i]], 1);
}

// Single-block exclusive scan of indeg -> off (and cursor copy). off[N] = E.
__global__ __launch_bounds__(1024) void k_scan(const int* __restrict__ indeg,
                                               int* __restrict__ off,
                                               int* __restrict__ cursor, int N) {
    __shared__ int part[1024];
    int tid = threadIdx.x;
    int per = (N + 1023) / 1024;
    int base = tid * per;
    int s = 0;
    for (int i = 0; i < per; i++) {
        int idx = base + i;
        if (idx < N) s += indeg[idx];
    }
    part[tid] = s;
    __syncthreads();
    for (int o = 1; o < 1024; o <<= 1) {
        int v = (tid >= o) ? part[tid - o] : 0;
        __syncthreads();
        part[tid] += v;
        __syncthreads();
    }
    int run = (tid > 0) ? part[tid - 1] : 0;
    for (int i = 0; i < per; i++) {
        int idx = base + i;
        if (idx < N) {
            off[idx] = run;
            cursor[idx] = run;
            run += indeg[idx];
        }
    }
    if (tid == 1023) off[N] = part[1023];
}

__global__ void k_scatter(const int* __restrict__ src, const int* __restrict__ dst,
                          const int* __restrict__ et, int* __restrict__ cursor,
                          int* __restrict__ csr_src, int* __restrict__ csr_et, int E) {
    int i = blockIdx.x * blockDim.x + threadIdx.x;
    if (i >= E) return;
    int p = atomicAdd(&cursor[dst[i]], 1);
    csr_src[p] = src[i];
    csr_et[p] = et[i];
}

// Warp-per-node aggregation: pre[n] = norm[n] * sum_{e in in(n)} (h[src_e] + rel[et_e])
__global__ __launch_bounds__(256) void k_agg(
    const float4* __restrict__ h4, const float4* __restrict__ rel4,
    const int* __restrict__ off, const int* __restrict__ csr_src,
    const int* __restrict__ csr_et, const float* __restrict__ norm,
    float4* __restrict__ pre4, int N) {
    int gw   = (blockIdx.x * blockDim.x + threadIdx.x) >> 5;
    int lane = threadIdx.x & 31;
    if (gw >= N) return;
    int beg = off[gw], end = off[gw + 1];
    int c0 = lane, c1 = lane + 32;
    bool has1 = c1 < D4;
    float4 a0 = make_float4(0.f, 0.f, 0.f, 0.f);
    float4 a1 = make_float4(0.f, 0.f, 0.f, 0.f);
#pragma unroll 2
    for (int e = beg; e < end; ++e) {
        int s = csr_src[e], t = csr_et[e];
        const float4* hs = h4   + (size_t)s * D4;
        const float4* rp = rel4 + (size_t)t * D4;
        float4 hv = hs[c0];
        float4 rv = rp[c0];
        a0.x += hv.x + rv.x; a0.y += hv.y + rv.y;
        a0.z += hv.z + rv.z; a0.w += hv.w + rv.w;
        if (has1) {
            float4 h1v = hs[c1];
            float4 r1v = rp[c1];
            a1.x += h1v.x + r1v.x; a1.y += h1v.y + r1v.y;
            a1.z += h1v.z + r1v.z; a1.w += h1v.w + r1v.w;
        }
    }
    float nv = __ldg(norm + gw);
    a0.x *= nv; a0.y *= nv; a0.z *= nv; a0.w *= nv;
    float4* pd = pre4 + (size_t)gw * D4;
    pd[c0] = a0;
    if (has1) {
        a1.x *= nv; a1.y *= nv; a1.z *= nv; a1.w *= nv;
        pd[c1] = a1;
    }
}

// Split weights into bf16 hi/lo, transposed to [n][k], N padded to 256, fused K.
__global__ void k_prepB(const float* __restrict__ Wn, const float* __restrict__ Wl,
                        __nv_bfloat16* __restrict__ bhi, __nv_bfloat16* __restrict__ blo,
                        int total) {
    int idx = blockIdx.x * blockDim.x + threadIdx.x;
    if (idx >= total) return;
    int k = idx % KPAD;
    int n = (idx / KPAD) % NPAD;
    int l = idx / (KPAD * NPAD);
    float v = 0.f;
    if (n < D) {
        if (k < D)                        v = Wn[(size_t)l * D * D + (size_t)k * D + n];
        else if (k >= 256 && k < 256 + D) v = Wl[(size_t)l * D * D + (size_t)(k - 256) * D + n];
    }
    __nv_bfloat16 h = __float2bfloat16(v);
    bhi[idx] = h;
    blo[idx] = __float2bfloat16(v - __bfloat162float(h));
}

// ---------------------------------------------------------------------------
__device__ __forceinline__ void mma16816(float* c, const uint32_t* a, uint32_t b0, uint32_t b1) {
    asm volatile("mma.sync.aligned.m16n8k16.row.col.f32.bf16.bf16.f32 "
                 "{%0,%1,%2,%3}, {%4,%5,%6,%7}, {%8,%9}, {%0,%1,%2,%3};"
                 : "+f"(c[0]), "+f"(c[1]), "+f"(c[2]), "+f"(c[3])
                 : "r"(a[0]), "r"(a[1]), "r"(a[2]), "r"(a[3]), "r"(b0), "r"(b1));
}

__device__ __forceinline__ void split2(float a, float b, uint32_t& hi, uint32_t& lo) {
    asm("cvt.rn.bf16x2.f32 %0, %1, %2;" : "=r"(hi) : "f"(b), "f"(a));
    float ha = __uint_as_float(hi << 16);
    float hb = __uint_as_float(hi & 0xFFFF0000u);
    float la = a - ha, lb = b - hb;
    asm("cvt.rn.bf16x2.f32 %0, %1, %2;" : "=r"(lo) : "f"(lb), "f"(la));
}

// out = rrelu( pre @ Wn + h @ Wl )   via mma.sync bf16 split-3.
// NI_MAX=4: full 64-col tile; NI_MAX=1: narrow tail tile (cols 192..200).
template <int NI_MAX>
__global__ __launch_bounds__(256, 2)
void k_gemm_tc(const float* __restrict__ pre, const float* __restrict__ hin,
               const __nv_bfloat16* __restrict__ bhi, const __nv_bfloat16* __restrict__ blo,
               float* __restrict__ out, int M, int col0base) {
    extern __shared__ __align__(16) uint32_t sw[];
    int tid  = threadIdx.x;
    int wid  = tid >> 5;
    int lane = tid & 31;
    int g    = lane >> 2;
    int t    = lane & 3;
    int row0 = blockIdx.x * TILE_M;
    int col0 = col0base + blockIdx.y * TILE_N;

    int arow    = tid >> 1;
    int acol    = (tid & 1) * 32;
    int grow    = row0 + arow;
    bool rv     = grow < M;
    int bhalf   = tid >> 7;
    int bt      = tid & 127;
    int brow    = bt >> 1;
    int bcol    = (bt & 1) * 32;
    const __nv_bfloat16* bsrc0 = (bhalf ? blo : bhi) + (size_t)(col0 + brow) * KPAD + bcol;

    int m0w = (wid >> 1) * 32;
    int n0w = (wid & 1) * 32;

    float C[2][NI_MAX][4];
#pragma unroll
    for (int mi = 0; mi < 2; mi++)
#pragma unroll
        for (int ni = 0; ni < NI_MAX; ni++)
#pragma unroll
            for (int j = 0; j < 4; j++) C[mi][ni][j] = 0.f;

    float pa[8][4];
    uint4 pb[4];

    // ---- prefetch chunk 0 ----
    {
        const float* rp = pre + (size_t)grow * D;
#pragma unroll
        for (int g4 = 0; g4 < 4; ++g4) {
            int k0 = acol + g4 * 8;
#pragma unroll
            for (int j = 0; j < 8; ++j)
                pa[g4 * 2 + (j >> 2)][j & 3] = (rv && k0 + j < D) ? rp[k0 + j] : 0.f;
        }
#pragma unroll
        for (int j = 0; j < 4; ++j) pb[j] = ((const uint4*)bsrc0)[j];
    }

    for (int c = 0; c < NCHUNKS; ++c) {
        if (c > 0) __syncthreads();

        // ---- store staged data to smem ----
        {
            int wbase = arow * ROWW + acol / 2;
#pragma unroll
            for (int g4 = 0; g4 < 4; ++g4) {
                uint32_t hw[4], lw[4];
#pragma unroll
                for (int j = 0; j < 4; ++j)
                    split2(pa[g4 * 2 + (j >> 1)][(j & 1) * 2 + 0] ,
                           pa[g4 * 2 + (j >> 1)][(j & 1) * 2 + 1], hw[j], lw[j]);
                int wb = wbase + g4 * 4;
                *(uint2*)&sw[W_AH + wb]     = make_uint2(hw[0], hw[1]);
                *(uint2*)&sw[W_AH + wb + 2] = make_uint2(hw[2], hw[3]);
                *(uint2*)&sw[W_AL + wb]     = make_uint2(lw[0], lw[1]);
                *(uint2*)&sw[W_AL + wb + 2] = make_uint2(lw[2], lw[3]);
            }
            int bb = (bhalf ? W_BL : W_BH) + brow * ROWW + bcol / 2;
#pragma unroll
            for (int j = 0; j < 4; ++j) {
                *(uint2*)&sw[bb + j * 4]     = make_uint2(pb[j].x, pb[j].y);
                *(uint2*)&sw[bb + j * 4 + 2] = make_uint2(pb[j].z, pb[j].w);
            }
        }
        __syncthreads();

        // ---- prefetch next chunk ----
        if (c + 1 < NCHUNKS) {
            int cn = c + 1;
            const float* srcp = (cn < 4) ? pre : hin;
            int kofs = (cn & 3) * KCHUNK;
            const float* rp = srcp + (size_t)grow * D;
#pragma unroll
            for (int g4 = 0; g4 < 4; ++g4) {
                int k0 = kofs + acol + g4 * 8;
                if (rv && k0 + 7 < D) {
                    float4 x = *(const float4*)(rp + k0);
                    float4 y = *(const float4*)(rp + k0 + 4);
                    pa[g4 * 2 + 0][0] = x.x; pa[g4 * 2 + 0][1] = x.y;
                    pa[g4 * 2 + 0][2] = x.z; pa[g4 * 2 + 0][3] = x.w;
                    pa[g4 * 2 + 1][0] = y.x; pa[g4 * 2 + 1][1] = y.y;
                    pa[g4 * 2 + 1][2] = y.z; pa[g4 * 2 + 1][3] = y.w;
                } else {
#pragma unroll
                    for (int j = 0; j < 8; ++j)
                        pa[g4 * 2 + (j >> 2)][j & 3] = (rv && k0 + j < D) ? rp[k0 + j] : 0.f;
                }
            }
            const __nv_bfloat16* bs = bsrc0 + cn * KCHUNK;
#pragma unroll
            for (int j = 0; j < 4; ++j) pb[j] = ((const uint4*)bs)[j];
        }

        // ---- compute ----
#pragma unroll
        for (int p = 0; p < 3; ++p) {
            const uint32_t* Ap = sw + ((p == 1) ? W_AL : W_AH);
            const uint32_t* Bp = sw + ((p == 2) ? W_BL : W_BH);
#pragma unroll
            for (int s = 0; s < 4; ++s) {
                int wo = s * 8 + t;
                uint32_t af[2][4];
#pragma unroll
                for (int mi = 0; mi < 2; ++mi) {
                    int r = m0w + mi * 16 + g;
                    af[mi][0] = Ap[r * ROWW + wo];
                    af[mi][1] = Ap[(r + 8) * ROWW + wo];
                    af[mi][2] = Ap[r * ROWW + wo + 4];
                    af[mi][3] = Ap[(r + 8) * ROWW + wo + 4];
                }
#pragma unroll
                for (int ni = 0; ni < NI_MAX; ++ni) {
                    int n = n0w + ni * 8 + g;
                    uint32_t b0 = Bp[n * ROWW + wo];
                    uint32_t b1 = Bp[n * ROWW + wo + 4];
                    mma16816(C[0][ni], af[0], b0, b1);
                    mma16816(C[1][ni], af[1], b0, b1);
                }
            }
        }
    }

    // ---- epilogue: rrelu + store ----
#pragma unroll
    for (int mi = 0; mi < 2; ++mi) {
        int r0 = row0 + m0w + mi * 16 + g;
#pragma unroll
        for (int ni = 0; ni < NI_MAX; ++ni) {
            int cc = col0 + n0w + ni * 8 + t * 2;
            if (cc + 1 < D) {
                if (r0 < M) {
                    float v0 = C[mi][ni][0], v1 = C[mi][ni][1];
                    float2 o;
                    o.x = (v0 >= 0.f) ? v0 : v0 * RRELU_SLOPE;
                    o.y = (v1 >= 0.f) ? v1 : v1 * RRELU_SLOPE;
                    *(float2*)(out + (size_t)r0 * D + cc) = o;
                }
                if (r0 + 8 < M) {
                    float v2 = C[mi][ni][2], v3 = C[mi][ni][3];
                    float2 o;
                    o.x = (v2 >= 0.f) ? v2 : v2 * RRELU_SLOPE;
                    o.y = (v3 >= 0.f) ? v3 : v3 * RRELU_SLOPE;
                    *(float2*)(out + (size_t)(r0 + 8) * D + cc) = o;
                }
            }
        }
    }
}

// Rows with indeg==0: out[n] = rrelu(h[n] @ We)  (pre-row is zero there).
__global__ void k_fixup(const float* __restrict__ hin, const float* __restrict__ We,
                        const int* __restrict__ indeg, float* __restrict__ out, int M) {
    int n = blockIdx.x;
    if (n >= M) return;
    if (indeg[n] != 0) return;
    __shared__ float hrow[D];
    for (int k = threadIdx.x; k < D; k += blockDim.x) hrow[k] = hin[(size_t)n * D + k];
    __syncthreads();
    for (int j = threadIdx.x; j < D; j += blockDim.x) {
        float s = 0.f;
        for (int k = 0; k < D; ++k) s = fmaf(hrow[k], We[(size_t)k * D + j], s);
        out[(size_t)n * D + j] = (s >= 0.f) ? s : s * RRELU_SLOPE;
    }
}

// ---------------------------------------------------------------------------
extern "C" void kernel_launch(void* const* d_in, const int* in_sizes, int n_in,
                              void* d_out, int out_size) {
    const float* init  = (const float*)d_in[0];
    const float* rel   = (const float*)d_in[1];
    const float* Wn    = (const float*)d_in[2];
    const float* Wl    = (const float*)d_in[3];
    const float* We    = (const float*)d_in[4];
    const float* norm  = (const float*)d_in[5];
    const int*   src   = (const int*)d_in[6];
    const int*   dst   = (const int*)d_in[7];
    const int*   et    = (const int*)d_in[8];
    const int*   nid   = (const int*)d_in[9];

    int E = in_sizes[6];
    int N = in_sizes[9];
    int L = in_sizes[2] / (D * D);
    float* out = (float*)d_out;

    void *p;
    cudaGetSymbolAddress(&p, g_h0);      float* h0 = (float*)p;
    cudaGetSymbolAddress(&p, g_h1);      float* h1 = (float*)p;
    cudaGetSymbolAddress(&p, g_pre);     float* pre = (float*)p;
    cudaGetSymbolAddress(&p, g_indeg);   int* indeg = (int*)p;
    cudaGetSymbolAddress(&p, g_off);     int* off = (int*)p;
    cudaGetSymbolAddress(&p, g_cursor);  int* cursor = (int*)p;
    cudaGetSymbolAddress(&p, g_csr_src); int* csr_src = (int*)p;
    cudaGetSymbolAddress(&p, g_csr_et);  int* csr_et = (int*)p;
    cudaGetSymbolAddress(&p, g_Bhi);     __nv_bfloat16* Bhi = (__nv_bfloat16*)p;
    cudaGetSymbolAddress(&p, g_Blo);     __nv_bfloat16* Blo = (__nv_bfloat16*)p;

    cudaFuncSetAttribute(k_gemm_tc<4>, cudaFuncAttributeMaxDynamicSharedMemorySize, SMEM_DYN);
    cudaFuncSetAttribute(k_gemm_tc<1>, cudaFuncAttributeMaxDynamicSharedMemorySize, SMEM_DYN);

    int nd4 = N * D4;
    k_zero_int<<<(N + 255) / 256, 256>>>(indeg, N);
    k_gather<<<(nd4 + 255) / 256, 256>>>((const float4*)init, nid, (float4*)h0, nd4);
    k_indeg<<<(E + 255) / 256, 256>>>(dst, indeg, E);
    k_scan<<<1, 1024>>>(indeg, off, cursor, N);
    k_scatter<<<(E + 255) / 256, 256>>>(src, dst, et, cursor, csr_src, csr_et, E);

    int ptot = L * NPAD * KPAD;
    k_prepB<<<(ptot + 255) / 256, 256>>>(Wn, Wl, Bhi, Blo, ptot);

    const float* hin = h0;
    for (int l = 0; l < L; ++l) {
        float* hout = (l == L - 1) ? out : ((hin == h0) ? h1 : h0);

        int ab = (int)(((long long)N * 32 + 255) / 256);
        k_agg<<<ab, 256>>>((const float4*)hin, (const float4*)rel, off, csr_src,
                           csr_et, norm, (float4*)pre, N);

        const __nv_bfloat16* bh = Bhi + (size_t)l * NPAD * KPAD;
        const __nv_bfloat16* bl = Blo + (size_t)l * NPAD * KPAD;
        int gx = (N + TILE_M - 1) / TILE_M;
        dim3 gfull(gx, 3);
        k_gemm_tc<4><<<gfull, 256, SMEM_DYN>>>(pre, hin, bh, bl, hout, N, 0);
        dim3 gtail(gx, 1);
        k_gemm_tc<1><<<gtail, 256, SMEM_DYN>>>(pre, hin, bh, bl, hout, N, 192);

        k_fixup<<<N, 256>>>(hin, We + (size_t)l * D * D, indeg, hout, N);

        hin = hout;
    }
}